// round 10
// baseline (speedup 1.0000x reference)
#include <cuda_runtime.h>
#include <stdint.h>

#define NPTS  256
#define DIM   256
#define KNN   16
#define NB    128       // 2 rows/block, 512 threads (h=0/1 halves), independent blocks
#define EPSV  1e-12f
#define CHUNK 32        // dims staged per tile
#define NCH   (DIM / CHUNK)
#define TPAD  36        // tile row stride (floats): 32 + 4 pad -> conflict-free

__device__ float    g_part[NB];
__device__ unsigned g_done = 0;
typedef unsigned long long u64;

#define FMA2(acc, x, y) asm("fma.rn.f32x2 %0, %1, %2, %0;" : "+l"(acc) : "l"(x), "l"(y))
#define ADD2(a, b)      asm("add.rn.f32x2 %0, %0, %1;"     : "+l"(a)   : "l"(b))

__global__ __launch_bounds__(512, 1)
void k_fused(const float* __restrict__ yi, const float* __restrict__ yit,
             float* __restrict__ out) {
    __shared__ __align__(16) float s_tile[NPTS * TPAD];          // 36 KB
    __shared__ __align__(16) float s_n[2][DIM];                  // normalized yi rows
    __shared__ __align__(16) float s_t[2][DIM];                  // normalized yit rows
    __shared__ unsigned sk[2][NPTS];
    __shared__ float    red0[16], red1[16], red2[16];
    __shared__ float4   sh_par[2];   // ia, ic, rn, rt per row
    __shared__ float    sh_ds[2];    // dself per row
    __shared__ float    shred[16];
    __shared__ unsigned s_last;

    const int t   = threadIdx.x, b = blockIdx.x;
    const int h   = t >> 8;          // which row of the pair this half handles
    const int col = t & 255;
    const int w   = t >> 5, l = t & 31;
    const int row = 2 * b + h;

    // ---------------- Phase A: normalize row `row` (3 sums, one reduction) ----------------
    float a = yi [row * DIM + col];
    float c = yit[row * DIM + col];
    float paa = a * a, pcc = c * c, pac = a * c;
    #pragma unroll
    for (int o = 16; o; o >>= 1) {
        paa += __shfl_down_sync(0xffffffffu, paa, o);
        pcc += __shfl_down_sync(0xffffffffu, pcc, o);
        pac += __shfl_down_sync(0xffffffffu, pac, o);
    }
    if (l == 0) { red0[w] = paa; red1[w] = pcc; red2[w] = pac; }
    __syncthreads();
    if (t == h * 256) {              // one thread per half
        float sa = 0.f, sc = 0.f, sac = 0.f;
        #pragma unroll
        for (int m = 0; m < 8; m++) {
            sa  += red0[h * 8 + m];
            sc  += red1[h * 8 + m];
            sac += red2[h * 8 + m];
        }
        float ia = 1.0f / sqrtf(sa + EPSV);
        float ic = 1.0f / sqrtf(sc + EPSV);
        float rn = sa * ia * ia, rt = sc * ic * ic;
        sh_par[h] = make_float4(ia, ic, rn, rt);
        sh_ds[h]  = 0.5f * sqrtf(fmaxf(rn + rt - 2.f * ia * ic * sac, 0.f) + EPSV);
    }
    __syncthreads();
    float4 P = sh_par[h];            // ia, ic, rn, rt of this half's row
    s_n[h][col] = a * P.x;
    s_t[h][col] = c * P.y;
    // (ordered before first compute by the staging barrier inside the loop)

    // ---------------- Phase B: double-buffered staged fused norm + dual dot ----------------
    const float4* yi4 = (const float4*)yi;
    const ulonglong2* pn = (const ulonglong2*)s_n[h];
    const ulonglong2* pc = (const ulonglong2*)s_t[h];

    // fixed per-slot staging geometry (4 slots per thread)
    int r_i[4], k_i[4];
    const float4* gsrc[4];
    float* sdst[4];
    #pragma unroll
    for (int i = 0; i < 4; i++) {
        int lin = i * 512 + t;
        r_i[i] = lin >> 3;  k_i[i] = lin & 7;
        gsrc[i] = yi4 + r_i[i] * (DIM / 4) + k_i[i];
        sdst[i] = &s_tile[r_i[i] * TPAD + 4 * k_i[i]];
    }

    u64 dnx = 0, dny = 0, dtx = 0, dty = 0, ssx = 0, ssy = 0;

    // prologue: prefetch chunk 0
    float4 pf[4];
    #pragma unroll
    for (int i = 0; i < 4; i++) pf[i] = gsrc[i][0];

    for (int ch = 0; ch < NCH; ch++) {
        // drain prefetch into tile
        #pragma unroll
        for (int i = 0; i < 4; i++) *(float4*)sdst[i] = pf[i];
        __syncthreads();

        // issue next chunk's global loads: latency hidden behind compute + barrier
        if (ch + 1 < NCH) {
            #pragma unroll
            for (int i = 0; i < 4; i++) pf[i] = gsrc[i][(ch + 1) * 8];
        }

        const ulonglong2* tl = (const ulonglong2*)&s_tile[col * TPAD];
        #pragma unroll
        for (int q = 0; q < 8; q++) {
            ulonglong2 v = tl[q];                // dims of column `col`, conflict-free
            ulonglong2 A = pn[ch * 8 + q];       // warp-uniform -> LDS broadcast
            ulonglong2 C = pc[ch * 8 + q];
            FMA2(dnx, A.x, v.x);  FMA2(dny, A.y, v.y);
            FMA2(dtx, C.x, v.x);  FMA2(dty, C.y, v.y);
            FMA2(ssx, v.x, v.x);  FMA2(ssy, v.y, v.y);
        }
        __syncthreads();
    }

    ADD2(dnx, dny);  ADD2(dtx, dty);  ADD2(ssx, ssy);
    float nlo, nhi, tlo, thi, slo, shi;
    asm("mov.b64 {%0, %1}, %2;" : "=f"(nlo), "=f"(nhi) : "l"(dnx));
    asm("mov.b64 {%0, %1}, %2;" : "=f"(tlo), "=f"(thi) : "l"(dtx));
    asm("mov.b64 {%0, %1}, %2;" : "=f"(slo), "=f"(shi) : "l"(ssx));

    float ss  = slo + shi;
    float iac = 1.0f / sqrtf(ss + EPSV);
    float rnt = ss * iac * iac;
    float d1  = 0.5f * sqrtf(fmaxf(P.z + rnt - 2.f * ((nlo + nhi) * iac), 0.f) + EPSV);
    float d2  = 0.5f * sqrtf(fmaxf(P.w + rnt - 2.f * ((tlo + thi) * iac), 0.f) + EPSV);

    unsigned key = __float_as_uint(d1);   // positive: bit order == value order
    sk[h][col] = key;
    __syncthreads();

    // ---------------- Parallel rank-count selection ----------------
    // Self distance is the row minimum; ranks 1..16 = K neighbors, rank 1 = second_nn.
    int rc = 0;
    const uint4* qk = (const uint4*)sk[h];
    #pragma unroll 8
    for (int q = 0; q < NPTS / 4; q++) {
        uint4 v = qk[q];                       // broadcast LDS.128
        rc += (v.x < key) + (v.y < key) + (v.z < key) + (v.w < key);
    }

    float contrib = 0.f;
    if (rc >= 1 && rc <= KNN) {
        float df = d1 - d2;
        contrib = df * df;
        if (rc == 1) contrib += fmaxf(sh_ds[h] + 0.6f - d1, 0.f);
    }

    #pragma unroll
    for (int o = 16; o; o >>= 1) contrib += __shfl_down_sync(0xffffffffu, contrib, o);
    if (l == 0) shred[w] = contrib;
    __syncthreads();
    if (t == 0) {
        float s = 0.f;
        #pragma unroll
        for (int m = 0; m < 16; m++) s += shred[m];
        g_part[b] = s - 2.0f * (float)KNN * 0.0025f;   // both rows' -K*T
    }

    // ---------------- last arriving block: deterministic final reduce ----------------
    __threadfence();
    __syncthreads();
    if (t == 0) s_last = atomicAdd(&g_done, 1);
    __syncthreads();
    if (s_last == NB - 1) {
        float v = (t < NB) ? *((volatile float*)&g_part[t]) : 0.f;
        #pragma unroll
        for (int o = 16; o; o >>= 1) v += __shfl_down_sync(0xffffffffu, v, o);
        if (l == 0) shred[w] = v;
        __syncthreads();
        if (t == 0) {
            float s = 0.f;
            #pragma unroll
            for (int m = 0; m < 16; m++) s += shred[m];
            out[0] = s;
            *((volatile unsigned*)&g_done) = 0;   // reset for next graph replay
        }
    }
}

extern "C" void kernel_launch(void* const* d_in, const int* in_sizes, int n_in,
                              void* d_out, int out_size) {
    const float* yi  = (const float*)d_in[0];
    const float* yit = (const float*)d_in[1];
    k_fused<<<NB, 512>>>(yi, yit, (float*)d_out);
}

// round 11
// speedup vs baseline: 1.6072x; 1.6072x over previous
#include <cuda_runtime.h>
#include <stdint.h>

#define NPTS  256
#define DIM   256
#define KNN   16
#define NB    128       // 2 rows/block, 512 threads (h=0/1 halves), independent blocks
#define EPSV  1e-12f
#define CHUNK 32        // dims staged per tile
#define NCH   (DIM / CHUNK)
#define TPAD  36        // tile row stride (floats): conflict-free for 8-lane LDS.128 phases

__device__ float    g_part[NB];
__device__ unsigned g_done = 0;
typedef unsigned long long u64;

#define FMA2(acc, x, y) asm("fma.rn.f32x2 %0, %1, %2, %0;" : "+l"(acc) : "l"(x), "l"(y))
#define ADD2(a, b)      asm("add.rn.f32x2 %0, %0, %1;"     : "+l"(a)   : "l"(b))

__global__ __launch_bounds__(512, 1)
void k_fused(const float* __restrict__ yi, const float* __restrict__ yit,
             float* __restrict__ out) {
    __shared__ __align__(16) float s_tile[NPTS * TPAD];          // 36 KB
    __shared__ __align__(16) float s_n[2][DIM];                  // normalized yi rows
    __shared__ __align__(16) float s_t[2][DIM];                  // normalized yit rows
    __shared__ unsigned sk[2][NPTS];
    __shared__ float    red0[16], red1[16], red2[16];
    __shared__ float4   sh_par[2];   // ia, ic, rn, rt per row
    __shared__ float    sh_ds[2];    // dself per row
    __shared__ float    shred[16];
    __shared__ unsigned s_last;

    const int t   = threadIdx.x, b = blockIdx.x;
    const int h   = t >> 8;          // which row of the pair this half handles
    const int col = t & 255;
    const int w   = t >> 5, l = t & 31;
    const int row = 2 * b + h;

    // ---------------- Phase A: normalize row `row` (3 sums, one reduction) ----------------
    float a = yi [row * DIM + col];
    float c = yit[row * DIM + col];
    float paa = a * a, pcc = c * c, pac = a * c;
    #pragma unroll
    for (int o = 16; o; o >>= 1) {
        paa += __shfl_down_sync(0xffffffffu, paa, o);
        pcc += __shfl_down_sync(0xffffffffu, pcc, o);
        pac += __shfl_down_sync(0xffffffffu, pac, o);
    }
    if (l == 0) { red0[w] = paa; red1[w] = pcc; red2[w] = pac; }
    __syncthreads();
    if (t == h * 256) {              // one thread per half
        float sa = 0.f, sc = 0.f, sac = 0.f;
        #pragma unroll
        for (int m = 0; m < 8; m++) {
            sa  += red0[h * 8 + m];
            sc  += red1[h * 8 + m];
            sac += red2[h * 8 + m];
        }
        float ia = 1.0f / sqrtf(sa + EPSV);
        float ic = 1.0f / sqrtf(sc + EPSV);
        float rn = sa * ia * ia, rt = sc * ic * ic;
        sh_par[h] = make_float4(ia, ic, rn, rt);
        sh_ds[h]  = 0.5f * sqrtf(fmaxf(rn + rt - 2.f * ia * ic * sac, 0.f) + EPSV);
    }
    __syncthreads();
    float4 P = sh_par[h];            // ia, ic, rn, rt of this half's row
    s_n[h][col] = a * P.x;
    s_t[h][col] = c * P.y;
    // (ordered before first compute by the staging barrier below)

    // ---------------- Phase B: staged fused norm + dual dot, register prefetch ----------------
    const float4* yi4 = (const float4*)yi;
    const ulonglong2* pn = (const ulonglong2*)s_n[h];
    const ulonglong2* pc = (const ulonglong2*)s_t[h];

    // per-thread staging geometry as SCALARS (loop-invariant)
    const int lin0 = t,        r0i = lin0 >> 3, k0i = lin0 & 7;
    const int lin1 = 512 + t,  r1i = lin1 >> 3, k1i = lin1 & 7;
    const int lin2 = 1024 + t, r2i = lin2 >> 3, k2i = lin2 & 7;
    const int lin3 = 1536 + t, r3i = lin3 >> 3, k3i = lin3 & 7;
    const float4* gp0 = yi4 + r0i * (DIM / 4) + k0i;
    const float4* gp1 = yi4 + r1i * (DIM / 4) + k1i;
    const float4* gp2 = yi4 + r2i * (DIM / 4) + k2i;
    const float4* gp3 = yi4 + r3i * (DIM / 4) + k3i;
    float* sp0 = &s_tile[r0i * TPAD + 4 * k0i];
    float* sp1 = &s_tile[r1i * TPAD + 4 * k1i];
    float* sp2 = &s_tile[r2i * TPAD + 4 * k2i];
    float* sp3 = &s_tile[r3i * TPAD + 4 * k3i];

    u64 dnx = 0, dny = 0, dtx = 0, dty = 0, ssx = 0, ssy = 0;
    const ulonglong2* tl = (const ulonglong2*)&s_tile[col * TPAD];

    // prologue: prefetch chunk 0
    float4 pf0 = gp0[0], pf1 = gp1[0], pf2 = gp2[0], pf3 = gp3[0];

    #pragma unroll
    for (int ch = 0; ch < NCH; ch++) {
        // drain prefetch into the tile
        *(float4*)sp0 = pf0;  *(float4*)sp1 = pf1;
        *(float4*)sp2 = pf2;  *(float4*)sp3 = pf3;
        __syncthreads();

        // issue next chunk's loads NOW (ch is compile-time const after unroll)
        if (ch + 1 < NCH) {
            pf0 = gp0[(ch + 1) * 8];  pf1 = gp1[(ch + 1) * 8];
            pf2 = gp2[(ch + 1) * 8];  pf3 = gp3[(ch + 1) * 8];
        }

        #pragma unroll
        for (int q = 0; q < 8; q++) {
            ulonglong2 v = tl[q];                // column `col` dims, conflict-free
            ulonglong2 A = pn[ch * 8 + q];       // warp-uniform -> LDS broadcast
            ulonglong2 C = pc[ch * 8 + q];
            FMA2(dnx, A.x, v.x);  FMA2(dny, A.y, v.y);
            FMA2(dtx, C.x, v.x);  FMA2(dty, C.y, v.y);
            FMA2(ssx, v.x, v.x);  FMA2(ssy, v.y, v.y);
        }
        __syncthreads();
    }

    ADD2(dnx, dny);  ADD2(dtx, dty);  ADD2(ssx, ssy);
    float nlo, nhi, tlo, thi, slo, shi;
    asm("mov.b64 {%0, %1}, %2;" : "=f"(nlo), "=f"(nhi) : "l"(dnx));
    asm("mov.b64 {%0, %1}, %2;" : "=f"(tlo), "=f"(thi) : "l"(dtx));
    asm("mov.b64 {%0, %1}, %2;" : "=f"(slo), "=f"(shi) : "l"(ssx));

    float ss  = slo + shi;
    float iac = 1.0f / sqrtf(ss + EPSV);
    float rnt = ss * iac * iac;
    float d1  = 0.5f * sqrtf(fmaxf(P.z + rnt - 2.f * ((nlo + nhi) * iac), 0.f) + EPSV);
    float d2  = 0.5f * sqrtf(fmaxf(P.w + rnt - 2.f * ((tlo + thi) * iac), 0.f) + EPSV);

    unsigned key = __float_as_uint(d1);   // positive: bit order == value order
    sk[h][col] = key;
    __syncthreads();

    // ---------------- Parallel rank-count selection ----------------
    // Self distance is the row minimum; ranks 1..16 = K neighbors, rank 1 = second_nn.
    int rc = 0;
    const uint4* qk = (const uint4*)sk[h];
    #pragma unroll 8
    for (int q = 0; q < NPTS / 4; q++) {
        uint4 v = qk[q];                       // broadcast LDS.128
        rc += (v.x < key) + (v.y < key) + (v.z < key) + (v.w < key);
    }

    float contrib = 0.f;
    if (rc >= 1 && rc <= KNN) {
        float df = d1 - d2;
        contrib = df * df;
        if (rc == 1) contrib += fmaxf(sh_ds[h] + 0.6f - d1, 0.f);
    }

    #pragma unroll
    for (int o = 16; o; o >>= 1) contrib += __shfl_down_sync(0xffffffffu, contrib, o);
    if (l == 0) shred[w] = contrib;
    __syncthreads();
    if (t == 0) {
        float s = 0.f;
        #pragma unroll
        for (int m = 0; m < 16; m++) s += shred[m];
        g_part[b] = s - 2.0f * (float)KNN * 0.0025f;   // both rows' -K*T
    }

    // ---------------- last arriving block: deterministic final reduce ----------------
    __threadfence();
    __syncthreads();
    if (t == 0) s_last = atomicAdd(&g_done, 1);
    __syncthreads();
    if (s_last == NB - 1) {
        float v = (t < NB) ? *((volatile float*)&g_part[t]) : 0.f;
        #pragma unroll
        for (int o = 16; o; o >>= 1) v += __shfl_down_sync(0xffffffffu, v, o);
        if (l == 0) shred[w] = v;
        __syncthreads();
        if (t == 0) {
            float s = 0.f;
            #pragma unroll
            for (int m = 0; m < 16; m++) s += shred[m];
            out[0] = s;
            *((volatile unsigned*)&g_done) = 0;   // reset for next graph replay
        }
    }
}

extern "C" void kernel_launch(void* const* d_in, const int* in_sizes, int n_in,
                              void* d_out, int out_size) {
    const float* yi  = (const float*)d_in[0];
    const float* yit = (const float*)d_in[1];
    k_fused<<<NB, 512>>>(yi, yit, (float*)d_out);
}